// round 15
// baseline (speedup 1.0000x reference)
#include <cuda_runtime.h>
#include <cuda_bf16.h>
#include <cstdint>
#include <math.h>

// Problem constants
#define Bn   8
#define Ln   1024
#define Vn   1024
#define Dn   2048
#define DVn  1024
#define KTOP 512
#define CAND_CAP 2048
#define HD   1024      // D/2
#define XD   4096      // 2*D
#define OUTL 1536      // L + K = V + K
#define KC   248       // Eigen multithreaded kc (frozen rounding boundary)
#define VBK  16        // visproj k-depth per smem buffer (2 sub-tiles of 8)
#define MARGIN 0.695f  // approx-sim candidate threshold (exact filter at 0.7f later)

// ---------------- static device scratch (no allocations allowed) ----------------
__device__ float g_visproj[Bn * Vn * Dn];                 // 67 MB (exact fp32)
__device__ float g_nl[Bn * Ln];                           // fp32 norms of lang rows
__device__ float g_nv[Bn * Vn];                           // fp32 norms of visproj rows
__device__ __nv_bfloat16 g_lh_hi[Bn * Ln * Dn];           // bf16 splits of lhat
__device__ __nv_bfloat16 g_lh_lo[Bn * Ln * Dn];
__device__ __nv_bfloat16 g_vh_hi[Bn * Vn * Dn];           // bf16 splits of vhat
__device__ __nv_bfloat16 g_vh_lo[Bn * Vn * Dn];
__device__ unsigned g_cidx[Bn * CAND_CAP];                // discovered candidate indices
__device__ unsigned long long g_ckey[Bn * CAND_CAP];      // exact sort keys
__device__ int g_cnt[Bn];                                 // discovery count (approx > MARGIN)
__device__ int g_cnt2[Bn];                                // exact count (> 0.7f)
__device__ int g_vl[Bn * KTOP];
__device__ int g_vv[Bn * KTOP];
__device__ int g_n[Bn];
__device__ int g_nkl[Bn];
__device__ int g_rml[Bn * OUTL];
__device__ int g_rmv[Bn * OUTL];
__device__ float g_h[Bn * KTOP * HD];                     // 16 MB
__device__ __nv_bfloat16 g_xhi[Bn * KTOP * XD];
__device__ __nv_bfloat16 g_xlo[Bn * KTOP * XD];
__device__ __nv_bfloat16 g_whi[HD * XD];
__device__ __nv_bfloat16 g_wlo[HD * XD];

// ---------------- f32x2 packed helpers ----------------
__device__ __forceinline__ unsigned long long dup_f32x2(float x) {
    unsigned long long r;
    asm("mov.b64 %0, {%1, %1};" : "=l"(r) : "r"(__float_as_uint(x)));
    return r;
}
__device__ __forceinline__ void fma_f32x2(unsigned long long& d,
                                          unsigned long long a, unsigned long long b) {
    asm("fma.rn.f32x2 %0, %1, %2, %0;" : "+l"(d) : "l"(a), "l"(b));
}
__device__ __forceinline__ void add_f32x2(unsigned long long& d, unsigned long long a) {
    asm("add.rn.f32x2 %0, %0, %1;" : "+l"(d) : "l"(a));
}
__device__ __forceinline__ float2 unpack_f32x2(unsigned long long v) {
    unsigned lo, hi;
    asm("mov.b64 {%0, %1}, %2;" : "=r"(lo), "=r"(hi) : "l"(v));
    return make_float2(__uint_as_float(lo), __uint_as_float(hi));
}

// ---------------- mma.sync helpers ----------------
__device__ __forceinline__ uint32_t s2u(const void* p) {
    return static_cast<uint32_t>(__cvta_generic_to_shared(p));
}
__device__ __forceinline__ void ldsm_x4(uint32_t& r0, uint32_t& r1, uint32_t& r2,
                                        uint32_t& r3, uint32_t addr) {
    asm volatile("ldmatrix.sync.aligned.m8n8.x4.shared.b16 {%0,%1,%2,%3}, [%4];"
                 : "=r"(r0), "=r"(r1), "=r"(r2), "=r"(r3) : "r"(addr));
}
__device__ __forceinline__ void mma_bf16(float c[4], const uint32_t a[4],
                                         const uint32_t b[2]) {
    asm volatile(
        "mma.sync.aligned.m16n8k16.row.col.f32.bf16.bf16.f32 "
        "{%0,%1,%2,%3}, {%4,%5,%6,%7}, {%8,%9}, {%0,%1,%2,%3};"
        : "+f"(c[0]), "+f"(c[1]), "+f"(c[2]), "+f"(c[3])
        : "r"(a[0]), "r"(a[1]), "r"(a[2]), "r"(a[3]), "r"(b[0]), "r"(b[1]));
}

// ---------------- kernels ----------------
__global__ void reset_counters() {
    if (threadIdx.x < Bn) { g_cnt[threadIdx.x] = 0; g_cnt2[threadIdx.x] = 0; }
}

// row norm (fp64 sum of squares, one fp32 rounding) + bf16 hi/lo splits of the
// normalized row. The fp32 normalized values themselves are NOT stored — rescore
// recomputes them bit-identically via __fdiv_rn(src, norm).
__global__ __launch_bounds__(256) void normalize_split(const float* __restrict__ src,
                                                       float* __restrict__ nrm,
                                                       __nv_bfloat16* __restrict__ hi,
                                                       __nv_bfloat16* __restrict__ lo) {
    long row = blockIdx.x;
    const float4* p4 = (const float4*)(src + row * Dn);
    int t = threadIdx.x;
    float4 a = p4[t];
    float4 b = p4[t + 256];
    double s = (double)a.x * a.x + (double)a.y * a.y + (double)a.z * a.z + (double)a.w * a.w
             + (double)b.x * b.x + (double)b.y * b.y + (double)b.z * b.z + (double)b.w * b.w;
    #pragma unroll
    for (int off = 16; off > 0; off >>= 1)
        s += __shfl_down_sync(0xFFFFFFFFu, s, off);
    __shared__ double ws[8];
    __shared__ float nsh;
    if ((t & 31) == 0) ws[t >> 5] = s;
    __syncthreads();
    if (t == 0) {
        double tot = ((ws[0] + ws[1]) + (ws[2] + ws[3])) + ((ws[4] + ws[5]) + (ws[6] + ws[7]));
        nsh = fmaxf((float)sqrt(tot), 1e-12f);
        nrm[row] = nsh;
    }
    __syncthreads();
    float n = nsh;
    a.x = __fdiv_rn(a.x, n); a.y = __fdiv_rn(a.y, n);
    a.z = __fdiv_rn(a.z, n); a.w = __fdiv_rn(a.w, n);
    b.x = __fdiv_rn(b.x, n); b.y = __fdiv_rn(b.y, n);
    b.z = __fdiv_rn(b.z, n); b.w = __fdiv_rn(b.w, n);
    float va[8] = { a.x, a.y, a.z, a.w, b.x, b.y, b.z, b.w };
    long base[2] = { row * Dn + (long)t * 4, row * Dn + (long)(t + 256) * 4 };
    #pragma unroll
    for (int g = 0; g < 2; g++) {
        __align__(8) __nv_bfloat16 h4[4], l4[4];
        #pragma unroll
        for (int e = 0; e < 4; e++) {
            float v = va[g * 4 + e];
            __nv_bfloat16 bh = __float2bfloat16(v);
            h4[e] = bh;
            l4[e] = __float2bfloat16(v - __bfloat162float(bh));
        }
        *(uint2*)(hi + base[g]) = *(const uint2*)h4;
        *(uint2*)(lo + base[g]) = *(const uint2*)l4;
    }
}

// vis_proj exact fp32 chunked GEMM — 512 threads, 128x128 tile, 8x4 outputs/thread,
// f32x2 row-pairing (A-pairs direct from smem; only 4 B dups/k), VBK=16 k-buffer
// (2 sub-tiles of 8 per __syncthreads -> half the barriers of BK=8).
// FROZEN ROUNDING: per-element sequential FMA chain, FADD folds at KC boundaries.
__global__ __launch_bounds__(512) void gemm_visproj(const float* __restrict__ vision,
                                                    const float* __restrict__ Wv2l,
                                                    const float* __restrict__ bv2l) {
    __shared__ float sA[2][VBK * 128];
    __shared__ float sB[2][VBK * 128];
    const int tid = threadIdx.x;
    const int b = blockIdx.z;
    // staging role: tid<256 stages A, else B (two float4 per thread per k-buffer)
    const int srow = (tid & 255) >> 1;
    const int slk  = (tid & 1) << 2;     // k-phases slk and slk+8
    const bool isA = tid < 256;
    const float* Srow = isA
        ? vision + ((long)b * Vn + blockIdx.y * 128 + srow) * DVn + slk
        : Wv2l + ((long)blockIdx.x * 128 + srow) * DVn + slk;
    // compute mapping: 8 rows x 4 cols per thread (rows paired in f32x2 lanes)
    const int ty = (tid >> 5) << 3;   // 0..120 (warp-uniform)
    const int tx = (tid & 31) << 2;   // 0..124

    unsigned long long tot[4][4], cur[4][4];   // [row-pair][col]
    #pragma unroll
    for (int pi = 0; pi < 4; pi++)
        #pragma unroll
        for (int j = 0; j < 4; j++) { tot[pi][j] = 0ULL; cur[pi][j] = 0ULL; }

    float4 pv0 = *(const float4*)(Srow);
    float4 pv1 = *(const float4*)(Srow + 8);
    {
        float* S = isA ? sA[0] : sB[0];
        S[(slk + 0) * 128 + srow] = pv0.x;
        S[(slk + 1) * 128 + srow] = pv0.y;
        S[(slk + 2) * 128 + srow] = pv0.z;
        S[(slk + 3) * 128 + srow] = pv0.w;
        S[(slk + 8) * 128 + srow] = pv1.x;
        S[(slk + 9) * 128 + srow] = pv1.y;
        S[(slk + 10) * 128 + srow] = pv1.z;
        S[(slk + 11) * 128 + srow] = pv1.w;
    }
    __syncthreads();

    int buf = 0;
    for (int kb = 0; kb < DVn; kb += VBK) {
        const bool has_next = (kb + VBK) < DVn;
        if (has_next) {
            pv0 = *(const float4*)(Srow + kb + VBK);
            pv1 = *(const float4*)(Srow + kb + VBK + 8);
        }
        #pragma unroll
        for (int s = 0; s < 2; s++) {
            #pragma unroll
            for (int k8 = 0; k8 < 8; k8++) {
                const int kl = s * 8 + k8;
                ulonglong2 ap01 = *(const ulonglong2*)(&sA[buf][kl * 128 + ty]);
                ulonglong2 ap23 = *(const ulonglong2*)(&sA[buf][kl * 128 + ty + 4]);
                unsigned long long ap[4] = { ap01.x, ap01.y, ap23.x, ap23.y };
                float4 bv = *(const float4*)(&sB[buf][kl * 128 + tx]);
                unsigned long long bd[4];
                bd[0] = dup_f32x2(bv.x); bd[1] = dup_f32x2(bv.y);
                bd[2] = dup_f32x2(bv.z); bd[3] = dup_f32x2(bv.w);
                #pragma unroll
                for (int pi = 0; pi < 4; pi++)
                    #pragma unroll
                    for (int j = 0; j < 4; j++)
                        fma_f32x2(cur[pi][j], ap[pi], bd[j]);
            }
            const int kend = kb + s * 8 + 8;
            if ((kend % KC) == 0 || kend == DVn) {   // chunk boundary: fold
                #pragma unroll
                for (int pi = 0; pi < 4; pi++)
                    #pragma unroll
                    for (int j = 0; j < 4; j++) {
                        add_f32x2(tot[pi][j], cur[pi][j]);
                        cur[pi][j] = 0ULL;
                    }
            }
        }
        if (has_next) {
            buf ^= 1;
            float* S = isA ? sA[buf] : sB[buf];
            S[(slk + 0) * 128 + srow] = pv0.x;
            S[(slk + 1) * 128 + srow] = pv0.y;
            S[(slk + 2) * 128 + srow] = pv0.z;
            S[(slk + 3) * 128 + srow] = pv0.w;
            S[(slk + 8) * 128 + srow] = pv1.x;
            S[(slk + 9) * 128 + srow] = pv1.y;
            S[(slk + 10) * 128 + srow] = pv1.z;
            S[(slk + 11) * 128 + srow] = pv1.w;
            __syncthreads();
        }
    }

    const int m0 = blockIdx.y * 128 + ty;
    const int n0 = blockIdx.x * 128 + tx;
    float* C = g_visproj + (long)b * Vn * Dn;
    #pragma unroll
    for (int pi = 0; pi < 4; pi++)
        #pragma unroll
        for (int j = 0; j < 4; j++) {
            float2 v = unpack_f32x2(tot[pi][j]);   // lo = row 2pi, hi = row 2pi+1
            float bias = bv2l[n0 + j];
            C[(long)(m0 + 2 * pi) * Dn + n0 + j]     = __fadd_rn(v.x, bias);
            C[(long)(m0 + 2 * pi + 1) * Dn + n0 + j] = __fadd_rn(v.y, bias);
        }
}

// sim via split-bf16 HMMA (3 segments). Emits approx sim (within 1e-5) and collects
// candidates with margin; exact ordering restored by rescore().
#define SIM_NIT 192   // 3 segs * (2048/32)
__global__ __launch_bounds__(256) void sim_tc(float* __restrict__ simout) {
    __shared__ __nv_bfloat16 sA[2][128][40];
    __shared__ __nv_bfloat16 sB[2][128][40];
    const int tid = threadIdx.x, warp = tid >> 5, lane = tid & 31;
    const int wm = warp >> 1, wn = warp & 1;
    const int b = blockIdx.z;

    float acc[2][8][4];
    #pragma unroll
    for (int mt = 0; mt < 2; mt++)
        #pragma unroll
        for (int nt = 0; nt < 8; nt++)
            #pragma unroll
            for (int c = 0; c < 4; c++) acc[mt][nt][c] = 0.f;

    uint4 pa[2], pb[2];
    auto fetch = [&](int it) {
        int seg = it >> 6;                 // 0: hi*hi, 1: hi*lo, 2: lo*hi
        int kb = (it & 63) << 5;
        const __nv_bfloat16* As = ((seg == 2) ? g_lh_lo : g_lh_hi)
                                  + ((long)b * Ln + blockIdx.y * 128) * Dn + kb;
        const __nv_bfloat16* Bs = ((seg == 1) ? g_vh_lo : g_vh_hi)
                                  + ((long)b * Vn + blockIdx.x * 128) * Dn + kb;
        #pragma unroll
        for (int q = 0; q < 2; q++) {
            int s = tid + q * 256, row = s >> 2, kq = (s & 3) << 3;
            pa[q] = *(const uint4*)(As + (long)row * Dn + kq);
            pb[q] = *(const uint4*)(Bs + (long)row * Dn + kq);
        }
    };
    auto stage = [&](int bf) {
        #pragma unroll
        for (int q = 0; q < 2; q++) {
            int s = tid + q * 256, row = s >> 2, kq = (s & 3) << 3;
            *(uint4*)&sA[bf][row][kq] = pa[q];
            *(uint4*)&sB[bf][row][kq] = pb[q];
        }
    };

    fetch(0); stage(0); __syncthreads();
    int buf = 0;
    for (int it = 0; it < SIM_NIT; it++) {
        const bool has_next = (it + 1) < SIM_NIT;
        if (has_next) fetch(it + 1);
        #pragma unroll
        for (int ks = 0; ks < 32; ks += 16) {
            uint32_t a[2][4], bb[8][2];
            #pragma unroll
            for (int mt = 0; mt < 2; mt++) {
                int row = wm * 32 + mt * 16 + (lane & 15);
                int col = ks + ((lane & 16) ? 8 : 0);
                ldsm_x4(a[mt][0], a[mt][1], a[mt][2], a[mt][3], s2u(&sA[buf][row][col]));
            }
            #pragma unroll
            for (int np = 0; np < 4; np++) {
                int row = wn * 64 + np * 16 + (lane & 7) + ((lane & 16) ? 8 : 0);
                int col = ks + ((lane & 8) ? 8 : 0);
                uint32_t t0, t1, t2, t3;
                ldsm_x4(t0, t1, t2, t3, s2u(&sB[buf][row][col]));
                bb[np * 2][0] = t0;     bb[np * 2][1] = t1;
                bb[np * 2 + 1][0] = t2; bb[np * 2 + 1][1] = t3;
            }
            #pragma unroll
            for (int mt = 0; mt < 2; mt++)
                #pragma unroll
                for (int nt = 0; nt < 8; nt++)
                    mma_bf16(acc[mt][nt], a[mt], bb[nt]);
        }
        if (has_next) {
            stage(buf ^ 1);
            __syncthreads();
            buf ^= 1;
        }
    }

    const int row0 = blockIdx.y * 128 + wm * 32;
    const int col0 = blockIdx.x * 128 + wn * 64;
    float* C = simout + (long)b * Ln * Vn;
    #pragma unroll
    for (int mt = 0; mt < 2; mt++)
        #pragma unroll
        for (int nt = 0; nt < 8; nt++)
            #pragma unroll
            for (int c = 0; c < 4; c++) {
                int r = row0 + mt * 16 + (lane >> 2) + ((c >= 2) ? 8 : 0);
                int col = col0 + nt * 8 + ((lane & 3) << 1) + (c & 1);
                float v = __fmul_rn(acc[mt][nt][c], 10.0f);
                C[(long)r * Vn + col] = v;
                if (v > MARGIN) {
                    int pos = atomicAdd(&g_cnt[b], 1);
                    if (pos < CAND_CAP)
                        g_cidx[b * CAND_CAP + pos] = (unsigned)r * Vn + (unsigned)col;
                }
            }
}

// EXACT rescore: per candidate, serial Eigen-chunked FMA chain with on-the-fly
// __fdiv_rn normalization (bit-identical to dividing then storing), KC folds,
// *10.0f, filter > 0.7f. Reproduces reference sim bits.
__global__ __launch_bounds__(256) void rescore(const float* __restrict__ lang) {
    int b = blockIdx.y;
    int i = blockIdx.x * 256 + threadIdx.x;
    if (i >= CAND_CAP) return;
    int cnt = min(g_cnt[b], CAND_CAP);
    if (i >= cnt) { g_ckey[b * CAND_CAP + i] = 0ULL; return; }
    unsigned idx = g_cidx[b * CAND_CAP + i];
    int l = idx >> 10, v = idx & 1023;
    const float4* lp = (const float4*)(lang + ((long)b * Ln + l) * Dn);
    const float4* vp = (const float4*)(g_visproj + ((long)b * Vn + v) * Dn);
    const float nl = g_nl[b * Ln + l];
    const float nv = g_nv[b * Vn + v];
    float tot = 0.f;
    int k4 = 0;
    #pragma unroll 1
    for (int c = 0; c < 9; c++) {
        int len4 = (c < 8) ? (KC / 4) : ((Dn - 8 * KC) / 4);   // 62 or 16
        float cur = 0.f;
        #pragma unroll 2
        for (int j = 0; j < len4; j++, k4++) {
            float4 a = lp[k4], bb = vp[k4];
            cur = __fmaf_rn(__fdiv_rn(a.x, nl), __fdiv_rn(bb.x, nv), cur);
            cur = __fmaf_rn(__fdiv_rn(a.y, nl), __fdiv_rn(bb.y, nv), cur);
            cur = __fmaf_rn(__fdiv_rn(a.z, nl), __fdiv_rn(bb.z, nv), cur);
            cur = __fmaf_rn(__fdiv_rn(a.w, nl), __fdiv_rn(bb.w, nv), cur);
        }
        tot = __fadd_rn(tot, cur);
    }
    float s = __fmul_rn(tot, 10.0f);
    unsigned long long key = 0ULL;
    if (s > 0.7f) {
        atomicAdd(&g_cnt2[b], 1);
        key = ((unsigned long long)__float_as_uint(s) << 20) | (unsigned)(~idx & 0xFFFFFu);
    }
    g_ckey[b * CAND_CAP + i] = key;
}

// per-batch bitonic sort of keys, descending
__global__ __launch_bounds__(1024) void sort_cand() {
    int b = blockIdx.x, t = threadIdx.x;
    __shared__ unsigned long long s[CAND_CAP];
    for (int i = t; i < CAND_CAP; i += 1024)
        s[i] = g_ckey[b * CAND_CAP + i];
    __syncthreads();
    for (int k = 2; k <= CAND_CAP; k <<= 1) {
        for (int j = k >> 1; j > 0; j >>= 1) {
            for (int i = t; i < CAND_CAP; i += 1024) {
                int ixj = i ^ j;
                if (ixj > i) {
                    bool up = ((i & k) == 0);
                    unsigned long long a = s[i], c = s[ixj];
                    if ((a < c) == up) { s[i] = c; s[ixj] = a; }
                }
            }
            __syncthreads();
        }
    }
    for (int i = t; i < CAND_CAP; i += 1024) g_ckey[b * CAND_CAP + i] = s[i];
}

__global__ void select_pairs() {
    int b = blockIdx.x, t = threadIdx.x;
    int n = min(g_cnt2[b], KTOP);
    if (t == 0) g_n[b] = n;
    if (t < n) {
        unsigned long long k = g_ckey[b * CAND_CAP + t];
        unsigned idx = (unsigned)(~k) & 0xFFFFFu;
        g_vl[b * KTOP + t] = idx >> 10;
        g_vv[b * KTOP + t] = idx & 1023;
    }
}

// build output row maps
__global__ __launch_bounds__(1024) void build_rowmap() {
    int b = blockIdx.x, t = threadIdx.x;
    __shared__ int flag[1024];
    __shared__ int scan[1024];
    int n = g_n[b];

    flag[t] = 0; __syncthreads();
    if (t < n) flag[g_vl[b * KTOP + t]] = 1;
    __syncthreads();
    int keep = 1 - flag[t];
    scan[t] = keep; __syncthreads();
    for (int off = 1; off < 1024; off <<= 1) {
        int v = (t >= off) ? scan[t - off] : 0;
        __syncthreads();
        scan[t] += v;
        __syncthreads();
    }
    int total = scan[1023];
    if (t == 0) g_nkl[b] = total;
    if (keep) g_rml[b * OUTL + scan[t] - 1] = t;
    for (int r = t; r < OUTL; r += 1024)
        if (r >= total) g_rml[b * OUTL + r] = (r < total + n) ? -2 : -1;
    __syncthreads();

    flag[t] = 0; __syncthreads();
    if (t < n) flag[g_vv[b * KTOP + t]] = 1;
    __syncthreads();
    keep = 1 - flag[t];
    scan[t] = keep; __syncthreads();
    for (int off = 1; off < 1024; off <<= 1) {
        int v = (t >= off) ? scan[t - off] : 0;
        __syncthreads();
        scan[t] += v;
        __syncthreads();
    }
    total = scan[1023];
    if (keep) g_rmv[b * OUTL + scan[t] - 1] = t;
    for (int r = t; r < OUTL; r += 1024)
        if (r >= total) g_rmv[b * OUTL + r] = -1;
    __syncthreads();
    if (t < n) g_rmv[b * OUTL + total + t] = g_vv[b * KTOP + t];
}

__global__ void copy_lang(const float* __restrict__ lang, float* __restrict__ out) {
    int r = blockIdx.x, b = blockIdx.y, t = threadIdx.x;
    int s = g_rml[b * OUTL + r];
    if (s == -2) return;
    float4* dst = (float4*)(out + ((long)b * OUTL + r) * Dn);
    if (s >= 0) {
        const float4* src = (const float4*)(lang + ((long)b * Ln + s) * Dn);
        for (int i = t; i < Dn / 4; i += 256) dst[i] = src[i];
    } else {
        float4 z = make_float4(0.f, 0.f, 0.f, 0.f);
        for (int i = t; i < Dn / 4; i += 256) dst[i] = z;
    }
}

__global__ void copy_vis(const float* __restrict__ vis, float* __restrict__ out) {
    int r = blockIdx.x, b = blockIdx.y, t = threadIdx.x;
    int s = g_rmv[b * OUTL + r];
    float4* dst = (float4*)(out + ((long)b * OUTL + r) * DVn);
    if (s >= 0) {
        const float4* src = (const float4*)(vis + ((long)b * Vn + s) * DVn);
        for (int i = t; i < DVn / 4; i += 256) dst[i] = src[i];
    } else {
        float4 z = make_float4(0.f, 0.f, 0.f, 0.f);
        for (int i = t; i < DVn / 4; i += 256) dst[i] = z;
    }
}

// split W_m1 into hi/lo bf16
__global__ __launch_bounds__(256) void split_w(const float* __restrict__ Wm1) {
    long r = blockIdx.x;
    const float* src = Wm1 + r * XD;
    __nv_bfloat16* hi = g_whi + r * XD;
    __nv_bfloat16* lo = g_wlo + r * XD;
    for (int k0 = threadIdx.x * 8; k0 < XD; k0 += 256 * 8) {
        float4 f0 = *(const float4*)(src + k0);
        float4 f1 = *(const float4*)(src + k0 + 4);
        float v[8] = { f0.x, f0.y, f0.z, f0.w, f1.x, f1.y, f1.z, f1.w };
        __align__(16) __nv_bfloat16 h8[8], l8[8];
        #pragma unroll
        for (int e = 0; e < 8; e++) {
            __nv_bfloat16 bh = __float2bfloat16(v[e]);
            h8[e] = bh;
            l8[e] = __float2bfloat16(v[e] - __bfloat162float(bh));
        }
        *(uint4*)(hi + k0) = *(const uint4*)h8;
        *(uint4*)(lo + k0) = *(const uint4*)l8;
    }
}

// gather + split x rows: x[r] = concat(lang[b, vl[i]], visproj[b, vv[i]])
__global__ __launch_bounds__(256) void gather_split_x(const float* __restrict__ lang) {
    int r = blockIdx.x;
    int b = r >> 9, i = r & (KTOP - 1);
    bool valid = (i < g_n[b]);
    const float* pl = lang + ((long)b * Ln + (valid ? g_vl[b * KTOP + i] : 0)) * Dn;
    const float* pv = g_visproj + ((long)b * Vn + (valid ? g_vv[b * KTOP + i] : 0)) * Dn;
    __nv_bfloat16* hi = g_xhi + (long)r * XD;
    __nv_bfloat16* lo = g_xlo + (long)r * XD;
    for (int k0 = threadIdx.x * 8; k0 < XD; k0 += 256 * 8) {
        float v[8] = {};
        if (valid) {
            const float* src = (k0 < Dn) ? (pl + k0) : (pv + (k0 - Dn));
            float4 f0 = *(const float4*)src;
            float4 f1 = *(const float4*)(src + 4);
            v[0]=f0.x; v[1]=f0.y; v[2]=f0.z; v[3]=f0.w;
            v[4]=f1.x; v[5]=f1.y; v[6]=f1.z; v[7]=f1.w;
        }
        __align__(16) __nv_bfloat16 h8[8], l8[8];
        #pragma unroll
        for (int e = 0; e < 8; e++) {
            __nv_bfloat16 bh = __float2bfloat16(v[e]);
            h8[e] = bh;
            l8[e] = __float2bfloat16(v[e] - __bfloat162float(bh));
        }
        *(uint4*)(hi + k0) = *(const uint4*)h8;
        *(uint4*)(lo + k0) = *(const uint4*)l8;
    }
}

// h = relu(x @ W_m1^T + b_m1) via bf16 HMMA (3 segments)
#define NIT 384
__global__ __launch_bounds__(256) void gemm_mlp_tc(const float* __restrict__ bm1) {
    __shared__ __nv_bfloat16 sA[2][128][40];
    __shared__ __nv_bfloat16 sB[2][128][40];
    const int tid = threadIdx.x, warp = tid >> 5, lane = tid & 31;
    const int wm = warp >> 1, wn = warp & 1;

    float acc[2][8][4];
    #pragma unroll
    for (int mt = 0; mt < 2; mt++)
        #pragma unroll
        for (int nt = 0; nt < 8; nt++)
            #pragma unroll
            for (int c = 0; c < 4; c++) acc[mt][nt][c] = 0.f;

    uint4 pa[2], pb[2];
    auto fetch = [&](int it) {
        int seg = it >> 7;
        int kb = (it & 127) << 5;
        const __nv_bfloat16* As = ((seg == 2) ? g_xlo : g_xhi)
                                  + ((long)blockIdx.y * 128) * XD + kb;
        const __nv_bfloat16* Bs = ((seg == 1) ? g_wlo : g_whi)
                                  + ((long)blockIdx.x * 128) * XD + kb;
        #pragma unroll
        for (int q = 0; q < 2; q++) {
            int s = tid + q * 256, row = s >> 2, kq = (s & 3) << 3;
            pa[q] = *(const uint4*)(As + (long)row * XD + kq);
            pb[q] = *(const uint4*)(Bs + (long)row * XD + kq);
        }
    };
    auto stage = [&](int bf) {
        #pragma unroll
        for (int q = 0; q < 2; q++) {
            int s = tid + q * 256, row = s >> 2, kq = (s & 3) << 3;
            *(uint4*)&sA[bf][row][kq] = pa[q];
            *(uint4*)&sB[bf][row][kq] = pb[q];
        }
    };

    fetch(0); stage(0); __syncthreads();
    int buf = 0;
    for (int it = 0; it < NIT; it++) {
        const bool has_next = (it + 1) < NIT;
        if (has_next) fetch(it + 1);
        #pragma unroll
        for (int ks = 0; ks < 32; ks += 16) {
            uint32_t a[2][4], bb[8][2];
            #pragma unroll
            for (int mt = 0; mt < 2; mt++) {
                int row = wm * 32 + mt * 16 + (lane & 15);
                int col = ks + ((lane & 16) ? 8 : 0);
                ldsm_x4(a[mt][0], a[mt][1], a[mt][2], a[mt][3], s2u(&sA[buf][row][col]));
            }
            #pragma unroll
            for (int np = 0; np < 4; np++) {
                int row = wn * 64 + np * 16 + (lane & 7) + ((lane & 16) ? 8 : 0);
                int col = ks + ((lane & 8) ? 8 : 0);
                uint32_t t0, t1, t2, t3;
                ldsm_x4(t0, t1, t2, t3, s2u(&sB[buf][row][col]));
                bb[np * 2][0] = t0;     bb[np * 2][1] = t1;
                bb[np * 2 + 1][0] = t2; bb[np * 2 + 1][1] = t3;
            }
            #pragma unroll
            for (int mt = 0; mt < 2; mt++)
                #pragma unroll
                for (int nt = 0; nt < 8; nt++)
                    mma_bf16(acc[mt][nt], a[mt], bb[nt]);
        }
        if (has_next) {
            stage(buf ^ 1);
            __syncthreads();
            buf ^= 1;
        }
    }

    const int row0 = blockIdx.y * 128 + wm * 32;
    const int col0 = blockIdx.x * 128 + wn * 64;
    #pragma unroll
    for (int mt = 0; mt < 2; mt++)
        #pragma unroll
        for (int nt = 0; nt < 8; nt++)
            #pragma unroll
            for (int c = 0; c < 4; c++) {
                int r = row0 + mt * 16 + (lane >> 2) + ((c >= 2) ? 8 : 0);
                int col = col0 + nt * 8 + ((lane & 3) << 1) + (c & 1);
                g_h[(long)r * HD + col] = fmaxf(acc[mt][nt][c] + bm1[col], 0.f);
            }
}

// logits = h @ W_m2^T + b_m2 ; softmax ; merged = w0*lt + w1*vt
__global__ void combine(const float* __restrict__ lang, const float* __restrict__ Wm2,
                        const float* __restrict__ bm2, float* __restrict__ out) {
    int i = blockIdx.x, b = blockIdx.y, t = threadIdx.x;
    if (i >= g_n[b]) return;
    const float* h = g_h + ((long)b * KTOP + i) * HD;
    float s0 = 0.f, s1 = 0.f;
    for (int k = t; k < HD; k += 256) {
        float hv = h[k];
        s0 += hv * Wm2[k];
        s1 += hv * Wm2[HD + k];
    }
    __shared__ float r0[256], r1[256];
    r0[t] = s0; r1[t] = s1; __syncthreads();
    for (int off = 128; off > 0; off >>= 1) {
        if (t < off) { r0[t] += r0[t + off]; r1[t] += r1[t + off]; }
        __syncthreads();
    }
    float l0 = r0[0] + bm2[0], l1 = r1[0] + bm2[1];
    float mx = fmaxf(l0, l1);
    float e0 = expf(l0 - mx), e1 = expf(l1 - mx);
    float w0 = __fdiv_rn(e0, e0 + e1), w1 = __fdiv_rn(e1, e0 + e1);
    int row = g_nkl[b] + i;
    float* dst = out + ((long)b * OUTL + row) * Dn;
    const float* lt = lang + ((long)b * Ln + g_vl[b * KTOP + i]) * Dn;
    const float* vt = g_visproj + ((long)b * Vn + g_vv[b * KTOP + i]) * Dn;
    for (int d = t; d < Dn; d += 256) dst[d] = w0 * lt[d] + w1 * vt[d];
}

// ---------------- host launch ----------------
extern "C" void kernel_launch(void* const* d_in, const int* in_sizes, int n_in,
                              void* d_out, int out_size) {
    const float* lang = (const float*)d_in[0];
    const float* vis  = (const float*)d_in[1];
    const float* Wv2l = (const float*)d_in[2];
    const float* bv2l = (const float*)d_in[3];
    const float* Wm1  = (const float*)d_in[4];
    const float* bm1  = (const float*)d_in[5];
    const float* Wm2  = (const float*)d_in[6];
    const float* bm2  = (const float*)d_in[7];

    float* out      = (float*)d_out;
    float* out_lang = out;                                   // [8,1536,2048]
    float* out_vis  = out + (long)Bn * OUTL * Dn;            // [8,1536,1024]
    float* out_sim  = out_vis + (long)Bn * OUTL * DVn;       // [8,1024,1024]

    float* vproj; cudaGetSymbolAddress((void**)&vproj, g_visproj);
    float* nl;    cudaGetSymbolAddress((void**)&nl, g_nl);
    float* nv;    cudaGetSymbolAddress((void**)&nv, g_nv);
    __nv_bfloat16 *lhhi, *lhlo, *vhhi, *vhlo;
    cudaGetSymbolAddress((void**)&lhhi, g_lh_hi);
    cudaGetSymbolAddress((void**)&lhlo, g_lh_lo);
    cudaGetSymbolAddress((void**)&vhhi, g_vh_hi);
    cudaGetSymbolAddress((void**)&vhlo, g_vh_lo);

    reset_counters<<<1, 32>>>();
    normalize_split<<<Bn * Ln, 256>>>(lang, nl, lhhi, lhlo);
    split_w<<<HD, 256>>>(Wm1);
    gemm_visproj<<<dim3(Dn / 128, Vn / 128, Bn), 512>>>(vis, Wv2l, bv2l);
    normalize_split<<<Bn * Vn, 256>>>(vproj, nv, vhhi, vhlo);
    sim_tc<<<dim3(Vn / 128, Ln / 128, Bn), 256>>>(out_sim);
    rescore<<<dim3(CAND_CAP / 256, Bn), 256>>>(lang);
    sort_cand<<<Bn, 1024>>>();
    select_pairs<<<Bn, KTOP>>>();
    build_rowmap<<<Bn, 1024>>>();
    copy_lang<<<dim3(OUTL, Bn), 256>>>(lang, out_lang);
    copy_vis<<<dim3(OUTL, Bn), 256>>>(vis, out_vis);
    gather_split_x<<<Bn * KTOP, 256>>>(lang);
    gemm_mlp_tc<<<dim3(HD / 128, (Bn * KTOP) / 128), 256>>>(bm1);
    combine<<<dim3(KTOP, Bn), 256>>>(lang, Wm2, bm2, out_lang);
}

// round 16
// speedup vs baseline: 1.0637x; 1.0637x over previous
#include <cuda_runtime.h>
#include <cuda_bf16.h>
#include <cstdint>
#include <math.h>

// Problem constants
#define Bn   8
#define Ln   1024
#define Vn   1024
#define Dn   2048
#define DVn  1024
#define KTOP 512
#define CAND_CAP 2048
#define HD   1024      // D/2
#define XD   4096      // 2*D
#define OUTL 1536      // L + K = V + K
#define KC   248       // Eigen multithreaded kc (frozen rounding boundary)
#define MARGIN 0.695f  // approx-sim candidate threshold (exact filter at 0.7f later)

// ---------------- static device scratch (no allocations allowed) ----------------
__device__ float g_visproj[Bn * Vn * Dn];                 // 67 MB (exact fp32)
__device__ float g_lhat[Bn * Ln * Dn];                    // exact normalized lang
__device__ float g_vhat[Bn * Vn * Dn];                    // exact normalized visproj
__device__ __nv_bfloat16 g_lh_hi[Bn * Ln * Dn];           // bf16 splits of lhat
__device__ __nv_bfloat16 g_lh_lo[Bn * Ln * Dn];
__device__ __nv_bfloat16 g_vh_hi[Bn * Vn * Dn];           // bf16 splits of vhat
__device__ __nv_bfloat16 g_vh_lo[Bn * Vn * Dn];
__device__ unsigned g_cidx[Bn * CAND_CAP];                // discovered candidate indices
__device__ unsigned long long g_ckey[Bn * CAND_CAP];      // exact sort keys
__device__ int g_cnt[Bn];                                 // discovery count (approx > MARGIN)
__device__ int g_cnt2[Bn];                                // exact count (> 0.7f)
__device__ int g_vl[Bn * KTOP];
__device__ int g_vv[Bn * KTOP];
__device__ int g_n[Bn];
__device__ int g_nkl[Bn];
__device__ int g_rml[Bn * OUTL];
__device__ int g_rmv[Bn * OUTL];
__device__ float g_h[Bn * KTOP * HD];                     // 16 MB
__device__ __nv_bfloat16 g_xhi[Bn * KTOP * XD];
__device__ __nv_bfloat16 g_xlo[Bn * KTOP * XD];
__device__ __nv_bfloat16 g_whi[HD * XD];
__device__ __nv_bfloat16 g_wlo[HD * XD];

// ---------------- f32x2 packed helpers ----------------
__device__ __forceinline__ unsigned long long dup_f32x2(float x) {
    unsigned long long r;
    asm("mov.b64 %0, {%1, %1};" : "=l"(r) : "r"(__float_as_uint(x)));
    return r;
}
__device__ __forceinline__ void fma_f32x2(unsigned long long& d,
                                          unsigned long long a, unsigned long long b) {
    asm("fma.rn.f32x2 %0, %1, %2, %0;" : "+l"(d) : "l"(a), "l"(b));
}
__device__ __forceinline__ void add_f32x2(unsigned long long& d, unsigned long long a) {
    asm("add.rn.f32x2 %0, %0, %1;" : "+l"(d) : "l"(a));
}
__device__ __forceinline__ float2 unpack_f32x2(unsigned long long v) {
    unsigned lo, hi;
    asm("mov.b64 {%0, %1}, %2;" : "=r"(lo), "=r"(hi) : "l"(v));
    return make_float2(__uint_as_float(lo), __uint_as_float(hi));
}

// ---------------- mma.sync helpers ----------------
__device__ __forceinline__ uint32_t s2u(const void* p) {
    return static_cast<uint32_t>(__cvta_generic_to_shared(p));
}
__device__ __forceinline__ void ldsm_x4(uint32_t& r0, uint32_t& r1, uint32_t& r2,
                                        uint32_t& r3, uint32_t addr) {
    asm volatile("ldmatrix.sync.aligned.m8n8.x4.shared.b16 {%0,%1,%2,%3}, [%4];"
                 : "=r"(r0), "=r"(r1), "=r"(r2), "=r"(r3) : "r"(addr));
}
__device__ __forceinline__ void mma_bf16(float c[4], const uint32_t a[4],
                                         const uint32_t b[2]) {
    asm volatile(
        "mma.sync.aligned.m16n8k16.row.col.f32.bf16.bf16.f32 "
        "{%0,%1,%2,%3}, {%4,%5,%6,%7}, {%8,%9}, {%0,%1,%2,%3};"
        : "+f"(c[0]), "+f"(c[1]), "+f"(c[2]), "+f"(c[3])
        : "r"(a[0]), "r"(a[1]), "r"(a[2]), "r"(a[3]), "r"(b[0]), "r"(b[1]));
}

// ---------------- kernels ----------------
__global__ void reset_counters() {
    if (threadIdx.x < Bn) { g_cnt[threadIdx.x] = 0; g_cnt2[threadIdx.x] = 0; }
}

// normalize rows (fp64 sum of squares, one fp32 rounding, __fdiv_rn elementwise)
// AND emit bf16 hi/lo splits of the normalized row.
__global__ __launch_bounds__(256) void normalize_split(const float* __restrict__ src,
                                                       float* __restrict__ dst,
                                                       __nv_bfloat16* __restrict__ hi,
                                                       __nv_bfloat16* __restrict__ lo) {
    long row = blockIdx.x;
    const float4* p4 = (const float4*)(src + row * Dn);
    int t = threadIdx.x;
    float4 a = p4[t];
    float4 b = p4[t + 256];
    double s = (double)a.x * a.x + (double)a.y * a.y + (double)a.z * a.z + (double)a.w * a.w
             + (double)b.x * b.x + (double)b.y * b.y + (double)b.z * b.z + (double)b.w * b.w;
    #pragma unroll
    for (int off = 16; off > 0; off >>= 1)
        s += __shfl_down_sync(0xFFFFFFFFu, s, off);
    __shared__ double ws[8];
    __shared__ float nsh;
    if ((t & 31) == 0) ws[t >> 5] = s;
    __syncthreads();
    if (t == 0) {
        double tot = ((ws[0] + ws[1]) + (ws[2] + ws[3])) + ((ws[4] + ws[5]) + (ws[6] + ws[7]));
        nsh = fmaxf((float)sqrt(tot), 1e-12f);
    }
    __syncthreads();
    float n = nsh;
    a.x = __fdiv_rn(a.x, n); a.y = __fdiv_rn(a.y, n);
    a.z = __fdiv_rn(a.z, n); a.w = __fdiv_rn(a.w, n);
    b.x = __fdiv_rn(b.x, n); b.y = __fdiv_rn(b.y, n);
    b.z = __fdiv_rn(b.z, n); b.w = __fdiv_rn(b.w, n);
    float4* d4 = (float4*)(dst + row * Dn);
    d4[t] = a;
    d4[t + 256] = b;
    float va[8] = { a.x, a.y, a.z, a.w, b.x, b.y, b.z, b.w };
    long base[2] = { row * Dn + (long)t * 4, row * Dn + (long)(t + 256) * 4 };
    #pragma unroll
    for (int g = 0; g < 2; g++) {
        __align__(8) __nv_bfloat16 h4[4], l4[4];
        #pragma unroll
        for (int e = 0; e < 4; e++) {
            float v = va[g * 4 + e];
            __nv_bfloat16 bh = __float2bfloat16(v);
            h4[e] = bh;
            l4[e] = __float2bfloat16(v - __bfloat162float(bh));
        }
        *(uint2*)(hi + base[g]) = *(const uint2*)h4;
        *(uint2*)(lo + base[g]) = *(const uint2*)l4;
    }
}

// vis_proj exact fp32 chunked GEMM — 512 threads, 128x128 tile, 8x4 outputs/thread.
// f32x2 lanes pair ROWS (i, i+1): A-pairs load directly from smem (broadcast,
// zero MOVs); only the 4 B scalars need duplication (8 MOV32/k).
// FROZEN ROUNDING: per-element sequential FMA chain, FADD folds at KC boundaries.
__global__ __launch_bounds__(512) void gemm_visproj(const float* __restrict__ vision,
                                                    const float* __restrict__ Wv2l,
                                                    const float* __restrict__ bv2l) {
    __shared__ float sA[2][8 * 128];
    __shared__ float sB[2][8 * 128];
    const int tid = threadIdx.x;
    const int b = blockIdx.z;
    const int srow = (tid & 255) >> 1;
    const int slk  = (tid & 1) << 2;
    const bool isA = tid < 256;
    const float* Srow = isA
        ? vision + ((long)b * Vn + blockIdx.y * 128 + srow) * DVn + slk
        : Wv2l + ((long)blockIdx.x * 128 + srow) * DVn + slk;
    const int ty = (tid >> 5) << 3;   // 0..120 (warp-uniform)
    const int tx = (tid & 31) << 2;   // 0..124

    unsigned long long tot[4][4], cur[4][4];   // [row-pair][col]
    #pragma unroll
    for (int pi = 0; pi < 4; pi++)
        #pragma unroll
        for (int j = 0; j < 4; j++) { tot[pi][j] = 0ULL; cur[pi][j] = 0ULL; }

    float4 pv = *(const float4*)(Srow);
    {
        float* S0 = isA ? sA[0] : sB[0];
        S0[(slk + 0) * 128 + srow] = pv.x;
        S0[(slk + 1) * 128 + srow] = pv.y;
        S0[(slk + 2) * 128 + srow] = pv.z;
        S0[(slk + 3) * 128 + srow] = pv.w;
    }
    __syncthreads();

    int buf = 0;
    for (int kt = 0; kt < DVn; kt += 8) {
        const bool has_next = (kt + 8) < DVn;
        if (has_next) pv = *(const float4*)(Srow + kt + 8);
        #pragma unroll
        for (int k = 0; k < 8; k++) {
            ulonglong2 ap01 = *(const ulonglong2*)(&sA[buf][k * 128 + ty]);
            ulonglong2 ap23 = *(const ulonglong2*)(&sA[buf][k * 128 + ty + 4]);
            unsigned long long ap[4] = { ap01.x, ap01.y, ap23.x, ap23.y };
            float4 bv = *(const float4*)(&sB[buf][k * 128 + tx]);
            unsigned long long bd[4];
            bd[0] = dup_f32x2(bv.x); bd[1] = dup_f32x2(bv.y);
            bd[2] = dup_f32x2(bv.z); bd[3] = dup_f32x2(bv.w);
            #pragma unroll
            for (int pi = 0; pi < 4; pi++)
                #pragma unroll
                for (int j = 0; j < 4; j++)
                    fma_f32x2(cur[pi][j], ap[pi], bd[j]);
        }
        const int kend = kt + 8;
        if ((kend % KC) == 0 || kend == DVn) {   // chunk boundary: fold into totals
            #pragma unroll
            for (int pi = 0; pi < 4; pi++)
                #pragma unroll
                for (int j = 0; j < 4; j++) {
                    add_f32x2(tot[pi][j], cur[pi][j]);
                    cur[pi][j] = 0ULL;
                }
        }
        if (has_next) {
            buf ^= 1;
            float* S = isA ? sA[buf] : sB[buf];
            S[(slk + 0) * 128 + srow] = pv.x;
            S[(slk + 1) * 128 + srow] = pv.y;
            S[(slk + 2) * 128 + srow] = pv.z;
            S[(slk + 3) * 128 + srow] = pv.w;
            __syncthreads();
        }
    }

    const int m0 = blockIdx.y * 128 + ty;
    const int n0 = blockIdx.x * 128 + tx;
    float* C = g_visproj + (long)b * Vn * Dn;
    #pragma unroll
    for (int pi = 0; pi < 4; pi++)
        #pragma unroll
        for (int j = 0; j < 4; j++) {
            float2 v = unpack_f32x2(tot[pi][j]);   // lo = row 2pi, hi = row 2pi+1
            float bias = bv2l[n0 + j];
            C[(long)(m0 + 2 * pi) * Dn + n0 + j]     = __fadd_rn(v.x, bias);
            C[(long)(m0 + 2 * pi + 1) * Dn + n0 + j] = __fadd_rn(v.y, bias);
        }
}

// sim via split-bf16 HMMA (3 segments). Emits approx sim (within 1e-5) and collects
// candidates with margin; exact ordering restored by rescore().
#define SIM_NIT 192   // 3 segs * (2048/32)
__global__ __launch_bounds__(256) void sim_tc(float* __restrict__ simout) {
    __shared__ __nv_bfloat16 sA[2][128][40];
    __shared__ __nv_bfloat16 sB[2][128][40];
    const int tid = threadIdx.x, warp = tid >> 5, lane = tid & 31;
    const int wm = warp >> 1, wn = warp & 1;
    const int b = blockIdx.z;

    float acc[2][8][4];
    #pragma unroll
    for (int mt = 0; mt < 2; mt++)
        #pragma unroll
        for (int nt = 0; nt < 8; nt++)
            #pragma unroll
            for (int c = 0; c < 4; c++) acc[mt][nt][c] = 0.f;

    uint4 pa[2], pb[2];
    auto fetch = [&](int it) {
        int seg = it >> 6;                 // 0: hi*hi, 1: hi*lo, 2: lo*hi
        int kb = (it & 63) << 5;
        const __nv_bfloat16* As = ((seg == 2) ? g_lh_lo : g_lh_hi)
                                  + ((long)b * Ln + blockIdx.y * 128) * Dn + kb;
        const __nv_bfloat16* Bs = ((seg == 1) ? g_vh_lo : g_vh_hi)
                                  + ((long)b * Vn + blockIdx.x * 128) * Dn + kb;
        #pragma unroll
        for (int q = 0; q < 2; q++) {
            int s = tid + q * 256, row = s >> 2, kq = (s & 3) << 3;
            pa[q] = *(const uint4*)(As + (long)row * Dn + kq);
            pb[q] = *(const uint4*)(Bs + (long)row * Dn + kq);
        }
    };
    auto stage = [&](int bf) {
        #pragma unroll
        for (int q = 0; q < 2; q++) {
            int s = tid + q * 256, row = s >> 2, kq = (s & 3) << 3;
            *(uint4*)&sA[bf][row][kq] = pa[q];
            *(uint4*)&sB[bf][row][kq] = pb[q];
        }
    };

    fetch(0); stage(0); __syncthreads();
    int buf = 0;
    for (int it = 0; it < SIM_NIT; it++) {
        const bool has_next = (it + 1) < SIM_NIT;
        if (has_next) fetch(it + 1);
        #pragma unroll
        for (int ks = 0; ks < 32; ks += 16) {
            uint32_t a[2][4], bb[8][2];
            #pragma unroll
            for (int mt = 0; mt < 2; mt++) {
                int row = wm * 32 + mt * 16 + (lane & 15);
                int col = ks + ((lane & 16) ? 8 : 0);
                ldsm_x4(a[mt][0], a[mt][1], a[mt][2], a[mt][3], s2u(&sA[buf][row][col]));
            }
            #pragma unroll
            for (int np = 0; np < 4; np++) {
                int row = wn * 64 + np * 16 + (lane & 7) + ((lane & 16) ? 8 : 0);
                int col = ks + ((lane & 8) ? 8 : 0);
                uint32_t t0, t1, t2, t3;
                ldsm_x4(t0, t1, t2, t3, s2u(&sB[buf][row][col]));
                bb[np * 2][0] = t0;     bb[np * 2][1] = t1;
                bb[np * 2 + 1][0] = t2; bb[np * 2 + 1][1] = t3;
            }
            #pragma unroll
            for (int mt = 0; mt < 2; mt++)
                #pragma unroll
                for (int nt = 0; nt < 8; nt++)
                    mma_bf16(acc[mt][nt], a[mt], bb[nt]);
        }
        if (has_next) {
            stage(buf ^ 1);
            __syncthreads();
            buf ^= 1;
        }
    }

    const int row0 = blockIdx.y * 128 + wm * 32;
    const int col0 = blockIdx.x * 128 + wn * 64;
    float* C = simout + (long)b * Ln * Vn;
    #pragma unroll
    for (int mt = 0; mt < 2; mt++)
        #pragma unroll
        for (int nt = 0; nt < 8; nt++)
            #pragma unroll
            for (int c = 0; c < 4; c++) {
                int r = row0 + mt * 16 + (lane >> 2) + ((c >= 2) ? 8 : 0);
                int col = col0 + nt * 8 + ((lane & 3) << 1) + (c & 1);
                float v = __fmul_rn(acc[mt][nt][c], 10.0f);
                C[(long)r * Vn + col] = v;
                if (v > MARGIN) {
                    int pos = atomicAdd(&g_cnt[b], 1);
                    if (pos < CAND_CAP)
                        g_cidx[b * CAND_CAP + pos] = (unsigned)r * Vn + (unsigned)col;
                }
            }
}

// EXACT rescore: per candidate, serial Eigen-chunked FMA chain over exact fp32
// lhat/vhat (KC folds), *10.0f, filter > 0.7f. Reproduces reference sim bits.
__global__ __launch_bounds__(256) void rescore() {
    int b = blockIdx.y;
    int i = blockIdx.x * 256 + threadIdx.x;
    if (i >= CAND_CAP) return;
    int cnt = min(g_cnt[b], CAND_CAP);
    if (i >= cnt) { g_ckey[b * CAND_CAP + i] = 0ULL; return; }
    unsigned idx = g_cidx[b * CAND_CAP + i];
    int l = idx >> 10, v = idx & 1023;
    const float4* lp = (const float4*)(g_lhat + ((long)b * Ln + l) * Dn);
    const float4* vp = (const float4*)(g_vhat + ((long)b * Vn + v) * Dn);
    float tot = 0.f;
    int k4 = 0;
    #pragma unroll 1
    for (int c = 0; c < 9; c++) {
        int len4 = (c < 8) ? (KC / 4) : ((Dn - 8 * KC) / 4);   // 62 or 16
        float cur = 0.f;
        #pragma unroll 2
        for (int j = 0; j < len4; j++, k4++) {
            float4 a = lp[k4], bb = vp[k4];
            cur = __fmaf_rn(a.x, bb.x, cur);
            cur = __fmaf_rn(a.y, bb.y, cur);
            cur = __fmaf_rn(a.z, bb.z, cur);
            cur = __fmaf_rn(a.w, bb.w, cur);
        }
        tot = __fadd_rn(tot, cur);
    }
    float s = __fmul_rn(tot, 10.0f);
    unsigned long long key = 0ULL;
    if (s > 0.7f) {
        atomicAdd(&g_cnt2[b], 1);
        key = ((unsigned long long)__float_as_uint(s) << 20) | (unsigned)(~idx & 0xFFFFFu);
    }
    g_ckey[b * CAND_CAP + i] = key;
}

// per-batch bitonic sort of keys, descending
__global__ __launch_bounds__(1024) void sort_cand() {
    int b = blockIdx.x, t = threadIdx.x;
    __shared__ unsigned long long s[CAND_CAP];
    for (int i = t; i < CAND_CAP; i += 1024)
        s[i] = g_ckey[b * CAND_CAP + i];
    __syncthreads();
    for (int k = 2; k <= CAND_CAP; k <<= 1) {
        for (int j = k >> 1; j > 0; j >>= 1) {
            for (int i = t; i < CAND_CAP; i += 1024) {
                int ixj = i ^ j;
                if (ixj > i) {
                    bool up = ((i & k) == 0);
                    unsigned long long a = s[i], c = s[ixj];
                    if ((a < c) == up) { s[i] = c; s[ixj] = a; }
                }
            }
            __syncthreads();
        }
    }
    for (int i = t; i < CAND_CAP; i += 1024) g_ckey[b * CAND_CAP + i] = s[i];
}

__global__ void select_pairs() {
    int b = blockIdx.x, t = threadIdx.x;
    int n = min(g_cnt2[b], KTOP);
    if (t == 0) g_n[b] = n;
    if (t < n) {
        unsigned long long k = g_ckey[b * CAND_CAP + t];
        unsigned idx = (unsigned)(~k) & 0xFFFFFu;
        g_vl[b * KTOP + t] = idx >> 10;
        g_vv[b * KTOP + t] = idx & 1023;
    }
}

// build output row maps
__global__ __launch_bounds__(1024) void build_rowmap() {
    int b = blockIdx.x, t = threadIdx.x;
    __shared__ int flag[1024];
    __shared__ int scan[1024];
    int n = g_n[b];

    flag[t] = 0; __syncthreads();
    if (t < n) flag[g_vl[b * KTOP + t]] = 1;
    __syncthreads();
    int keep = 1 - flag[t];
    scan[t] = keep; __syncthreads();
    for (int off = 1; off < 1024; off <<= 1) {
        int v = (t >= off) ? scan[t - off] : 0;
        __syncthreads();
        scan[t] += v;
        __syncthreads();
    }
    int total = scan[1023];
    if (t == 0) g_nkl[b] = total;
    if (keep) g_rml[b * OUTL + scan[t] - 1] = t;
    for (int r = t; r < OUTL; r += 1024)
        if (r >= total) g_rml[b * OUTL + r] = (r < total + n) ? -2 : -1;
    __syncthreads();

    flag[t] = 0; __syncthreads();
    if (t < n) flag[g_vv[b * KTOP + t]] = 1;
    __syncthreads();
    keep = 1 - flag[t];
    scan[t] = keep; __syncthreads();
    for (int off = 1; off < 1024; off <<= 1) {
        int v = (t >= off) ? scan[t - off] : 0;
        __syncthreads();
        scan[t] += v;
        __syncthreads();
    }
    total = scan[1023];
    if (keep) g_rmv[b * OUTL + scan[t] - 1] = t;
    for (int r = t; r < OUTL; r += 1024)
        if (r >= total) g_rmv[b * OUTL + r] = -1;
    __syncthreads();
    if (t < n) g_rmv[b * OUTL + total + t] = g_vv[b * KTOP + t];
}

__global__ void copy_lang(const float* __restrict__ lang, float* __restrict__ out) {
    int r = blockIdx.x, b = blockIdx.y, t = threadIdx.x;
    int s = g_rml[b * OUTL + r];
    if (s == -2) return;
    float4* dst = (float4*)(out + ((long)b * OUTL + r) * Dn);
    if (s >= 0) {
        const float4* src = (const float4*)(lang + ((long)b * Ln + s) * Dn);
        for (int i = t; i < Dn / 4; i += 256) dst[i] = src[i];
    } else {
        float4 z = make_float4(0.f, 0.f, 0.f, 0.f);
        for (int i = t; i < Dn / 4; i += 256) dst[i] = z;
    }
}

__global__ void copy_vis(const float* __restrict__ vis, float* __restrict__ out) {
    int r = blockIdx.x, b = blockIdx.y, t = threadIdx.x;
    int s = g_rmv[b * OUTL + r];
    float4* dst = (float4*)(out + ((long)b * OUTL + r) * DVn);
    if (s >= 0) {
        const float4* src = (const float4*)(vis + ((long)b * Vn + s) * DVn);
        for (int i = t; i < DVn / 4; i += 256) dst[i] = src[i];
    } else {
        float4 z = make_float4(0.f, 0.f, 0.f, 0.f);
        for (int i = t; i < DVn / 4; i += 256) dst[i] = z;
    }
}

// split W_m1 into hi/lo bf16
__global__ __launch_bounds__(256) void split_w(const float* __restrict__ Wm1) {
    long r = blockIdx.x;
    const float* src = Wm1 + r * XD;
    __nv_bfloat16* hi = g_whi + r * XD;
    __nv_bfloat16* lo = g_wlo + r * XD;
    for (int k0 = threadIdx.x * 8; k0 < XD; k0 += 256 * 8) {
        float4 f0 = *(const float4*)(src + k0);
        float4 f1 = *(const float4*)(src + k0 + 4);
        float v[8] = { f0.x, f0.y, f0.z, f0.w, f1.x, f1.y, f1.z, f1.w };
        __align__(16) __nv_bfloat16 h8[8], l8[8];
        #pragma unroll
        for (int e = 0; e < 8; e++) {
            __nv_bfloat16 bh = __float2bfloat16(v[e]);
            h8[e] = bh;
            l8[e] = __float2bfloat16(v[e] - __bfloat162float(bh));
        }
        *(uint4*)(hi + k0) = *(const uint4*)h8;
        *(uint4*)(lo + k0) = *(const uint4*)l8;
    }
}

// gather + split x rows: x[r] = concat(lang[b, vl[i]], visproj[b, vv[i]])
__global__ __launch_bounds__(256) void gather_split_x(const float* __restrict__ lang) {
    int r = blockIdx.x;
    int b = r >> 9, i = r & (KTOP - 1);
    bool valid = (i < g_n[b]);
    const float* pl = lang + ((long)b * Ln + (valid ? g_vl[b * KTOP + i] : 0)) * Dn;
    const float* pv = g_visproj + ((long)b * Vn + (valid ? g_vv[b * KTOP + i] : 0)) * Dn;
    __nv_bfloat16* hi = g_xhi + (long)r * XD;
    __nv_bfloat16* lo = g_xlo + (long)r * XD;
    for (int k0 = threadIdx.x * 8; k0 < XD; k0 += 256 * 8) {
        float v[8] = {};
        if (valid) {
            const float* src = (k0 < Dn) ? (pl + k0) : (pv + (k0 - Dn));
            float4 f0 = *(const float4*)src;
            float4 f1 = *(const float4*)(src + 4);
            v[0]=f0.x; v[1]=f0.y; v[2]=f0.z; v[3]=f0.w;
            v[4]=f1.x; v[5]=f1.y; v[6]=f1.z; v[7]=f1.w;
        }
        __align__(16) __nv_bfloat16 h8[8], l8[8];
        #pragma unroll
        for (int e = 0; e < 8; e++) {
            __nv_bfloat16 bh = __float2bfloat16(v[e]);
            h8[e] = bh;
            l8[e] = __float2bfloat16(v[e] - __bfloat162float(bh));
        }
        *(uint4*)(hi + k0) = *(const uint4*)h8;
        *(uint4*)(lo + k0) = *(const uint4*)l8;
    }
}

// h = relu(x @ W_m1^T + b_m1) via bf16 HMMA (3 segments)
#define NIT 384
__global__ __launch_bounds__(256) void gemm_mlp_tc(const float* __restrict__ bm1) {
    __shared__ __nv_bfloat16 sA[2][128][40];
    __shared__ __nv_bfloat16 sB[2][128][40];
    const int tid = threadIdx.x, warp = tid >> 5, lane = tid & 31;
    const int wm = warp >> 1, wn = warp & 1;

    float acc[2][8][4];
    #pragma unroll
    for (int mt = 0; mt < 2; mt++)
        #pragma unroll
        for (int nt = 0; nt < 8; nt++)
            #pragma unroll
            for (int c = 0; c < 4; c++) acc[mt][nt][c] = 0.f;

    uint4 pa[2], pb[2];
    auto fetch = [&](int it) {
        int seg = it >> 7;
        int kb = (it & 127) << 5;
        const __nv_bfloat16* As = ((seg == 2) ? g_xlo : g_xhi)
                                  + ((long)blockIdx.y * 128) * XD + kb;
        const __nv_bfloat16* Bs = ((seg == 1) ? g_wlo : g_whi)
                                  + ((long)blockIdx.x * 128) * XD + kb;
        #pragma unroll
        for (int q = 0; q < 2; q++) {
            int s = tid + q * 256, row = s >> 2, kq = (s & 3) << 3;
            pa[q] = *(const uint4*)(As + (long)row * XD + kq);
            pb[q] = *(const uint4*)(Bs + (long)row * XD + kq);
        }
    };
    auto stage = [&](int bf) {
        #pragma unroll
        for (int q = 0; q < 2; q++) {
            int s = tid + q * 256, row = s >> 2, kq = (s & 3) << 3;
            *(uint4*)&sA[bf][row][kq] = pa[q];
            *(uint4*)&sB[bf][row][kq] = pb[q];
        }
    };

    fetch(0); stage(0); __syncthreads();
    int buf = 0;
    for (int it = 0; it < NIT; it++) {
        const bool has_next = (it + 1) < NIT;
        if (has_next) fetch(it + 1);
        #pragma unroll
        for (int ks = 0; ks < 32; ks += 16) {
            uint32_t a[2][4], bb[8][2];
            #pragma unroll
            for (int mt = 0; mt < 2; mt++) {
                int row = wm * 32 + mt * 16 + (lane & 15);
                int col = ks + ((lane & 16) ? 8 : 0);
                ldsm_x4(a[mt][0], a[mt][1], a[mt][2], a[mt][3], s2u(&sA[buf][row][col]));
            }
            #pragma unroll
            for (int np = 0; np < 4; np++) {
                int row = wn * 64 + np * 16 + (lane & 7) + ((lane & 16) ? 8 : 0);
                int col = ks + ((lane & 8) ? 8 : 0);
                uint32_t t0, t1, t2, t3;
                ldsm_x4(t0, t1, t2, t3, s2u(&sB[buf][row][col]));
                bb[np * 2][0] = t0;     bb[np * 2][1] = t1;
                bb[np * 2 + 1][0] = t2; bb[np * 2 + 1][1] = t3;
            }
            #pragma unroll
            for (int mt = 0; mt < 2; mt++)
                #pragma unroll
                for (int nt = 0; nt < 8; nt++)
                    mma_bf16(acc[mt][nt], a[mt], bb[nt]);
        }
        if (has_next) {
            stage(buf ^ 1);
            __syncthreads();
            buf ^= 1;
        }
    }

    const int row0 = blockIdx.y * 128 + wm * 32;
    const int col0 = blockIdx.x * 128 + wn * 64;
    #pragma unroll
    for (int mt = 0; mt < 2; mt++)
        #pragma unroll
        for (int nt = 0; nt < 8; nt++)
            #pragma unroll
            for (int c = 0; c < 4; c++) {
                int r = row0 + mt * 16 + (lane >> 2) + ((c >= 2) ? 8 : 0);
                int col = col0 + nt * 8 + ((lane & 3) << 1) + (c & 1);
                g_h[(long)r * HD + col] = fmaxf(acc[mt][nt][c] + bm1[col], 0.f);
            }
}

// logits = h @ W_m2^T + b_m2 ; softmax ; merged = w0*lt + w1*vt
__global__ void combine(const float* __restrict__ lang, const float* __restrict__ Wm2,
                        const float* __restrict__ bm2, float* __restrict__ out) {
    int i = blockIdx.x, b = blockIdx.y, t = threadIdx.x;
    if (i >= g_n[b]) return;
    const float* h = g_h + ((long)b * KTOP + i) * HD;
    float s0 = 0.f, s1 = 0.f;
    for (int k = t; k < HD; k += 256) {
        float hv = h[k];
        s0 += hv * Wm2[k];
        s1 += hv * Wm2[HD + k];
    }
    __shared__ float r0[256], r1[256];
    r0[t] = s0; r1[t] = s1; __syncthreads();
    for (int off = 128; off > 0; off >>= 1) {
        if (t < off) { r0[t] += r0[t + off]; r1[t] += r1[t + off]; }
        __syncthreads();
    }
    float l0 = r0[0] + bm2[0], l1 = r1[0] + bm2[1];
    float mx = fmaxf(l0, l1);
    float e0 = expf(l0 - mx), e1 = expf(l1 - mx);
    float w0 = __fdiv_rn(e0, e0 + e1), w1 = __fdiv_rn(e1, e0 + e1);
    int row = g_nkl[b] + i;
    float* dst = out + ((long)b * OUTL + row) * Dn;
    const float* lt = lang + ((long)b * Ln + g_vl[b * KTOP + i]) * Dn;
    const float* vt = g_visproj + ((long)b * Vn + g_vv[b * KTOP + i]) * Dn;
    for (int d = t; d < Dn; d += 256) dst[d] = w0 * lt[d] + w1 * vt[d];
}

// ---------------- host launch (fork-join stream overlap, graph-capturable) ----------
static cudaStream_t g_s1 = nullptr;
static cudaEvent_t g_e0 = nullptr, g_e1 = nullptr, g_e2 = nullptr, g_e3 = nullptr;

extern "C" void kernel_launch(void* const* d_in, const int* in_sizes, int n_in,
                              void* d_out, int out_size) {
    const float* lang = (const float*)d_in[0];
    const float* vis  = (const float*)d_in[1];
    const float* Wv2l = (const float*)d_in[2];
    const float* bv2l = (const float*)d_in[3];
    const float* Wm1  = (const float*)d_in[4];
    const float* bm1  = (const float*)d_in[5];
    const float* Wm2  = (const float*)d_in[6];
    const float* bm2  = (const float*)d_in[7];

    float* out      = (float*)d_out;
    float* out_lang = out;                                   // [8,1536,2048]
    float* out_vis  = out + (long)Bn * OUTL * Dn;            // [8,1536,1024]
    float* out_sim  = out_vis + (long)Bn * OUTL * DVn;       // [8,1024,1024]

    float* lhat;  cudaGetSymbolAddress((void**)&lhat, g_lhat);
    float* vhat;  cudaGetSymbolAddress((void**)&vhat, g_vhat);
    float* vproj; cudaGetSymbolAddress((void**)&vproj, g_visproj);
    __nv_bfloat16 *lhhi, *lhlo, *vhhi, *vhlo;
    cudaGetSymbolAddress((void**)&lhhi, g_lh_hi);
    cudaGetSymbolAddress((void**)&lhlo, g_lh_lo);
    cudaGetSymbolAddress((void**)&vhhi, g_vh_hi);
    cudaGetSymbolAddress((void**)&vhlo, g_vh_lo);

    // one-time resource creation (first call = uncaptured correctness run;
    // captured calls replay identical work — no caching of results)
    if (g_s1 == nullptr) {
        cudaStreamCreateWithFlags(&g_s1, cudaStreamNonBlocking);
        cudaEventCreateWithFlags(&g_e0, cudaEventDisableTiming);
        cudaEventCreateWithFlags(&g_e1, cudaEventDisableTiming);
        cudaEventCreateWithFlags(&g_e2, cudaEventDisableTiming);
        cudaEventCreateWithFlags(&g_e3, cudaEventDisableTiming);
    }

    reset_counters<<<1, 32>>>();

    // fork: lang-normalize + W split run concurrently with the big visproj GEMM
    cudaEventRecord(g_e0, 0);
    cudaStreamWaitEvent(g_s1, g_e0, 0);
    normalize_split<<<Bn * Ln, 256, 0, g_s1>>>(lang, lhat, lhhi, lhlo);
    split_w<<<HD, 256, 0, g_s1>>>(Wm1);

    gemm_visproj<<<dim3(Dn / 128, Vn / 128, Bn), 512>>>(vis, Wv2l, bv2l);
    normalize_split<<<Bn * Vn, 256>>>(vproj, vhat, vhhi, vhlo);

    // join: sim needs lang splits (s1) and visproj splits (s0)
    cudaEventRecord(g_e1, g_s1);
    cudaStreamWaitEvent(0, g_e1, 0);

    sim_tc<<<dim3(Vn / 128, Ln / 128, Bn), 256>>>(out_sim);
    rescore<<<dim3(CAND_CAP / 256, Bn), 256>>>();
    sort_cand<<<Bn, 1024>>>();
    select_pairs<<<Bn, KTOP>>>();
    build_rowmap<<<Bn, 1024>>>();

    // fork: output copies are independent of the MLP chain
    cudaEventRecord(g_e2, 0);
    cudaStreamWaitEvent(g_s1, g_e2, 0);
    copy_lang<<<dim3(OUTL, Bn), 256, 0, g_s1>>>(lang, out_lang);
    copy_vis<<<dim3(OUTL, Bn), 256, 0, g_s1>>>(vis, out_vis);

    gather_split_x<<<Bn * KTOP, 256>>>(lang);
    gemm_mlp_tc<<<dim3(HD / 128, (Bn * KTOP) / 128), 256>>>(bm1);
    combine<<<dim3(KTOP, Bn), 256>>>(lang, Wm2, bm2, out_lang);

    // join before returning so the graph's end depends on the copies
    cudaEventRecord(g_e3, g_s1);
    cudaStreamWaitEvent(0, g_e3, 0);
}